// round 3
// baseline (speedup 1.0000x reference)
#include <cuda_runtime.h>

// SelfNorm collapsed: out = x*std_w + mean*(mean_w - std_w), per (b,c) row.
// One CTA per row. Row is read from DRAM exactly once, buffered in SMEM
// across a single barrier. All threads compute the tiny MLPs redundantly
// (no serial section). Streaming load/store hints keep L2 clean.

#define HW 3136          // 56*56
#define F4 784           // HW/4 = 3*256 + 16
#define NTHREADS 256
#define EPS 1e-5f

__device__ __forceinline__ float tiny_mlp(float mean, float std,
                                          const float* __restrict__ W1,
                                          const float* __restrict__ b1,
                                          const float* __restrict__ W2,
                                          const float* __restrict__ b2) {
    float z = __ldg(b2);
    #pragma unroll
    for (int o = 0; o < 16; o++) {
        float h = fmaf(__ldg(W1 + 2 * o), mean,
                  fmaf(__ldg(W1 + 2 * o + 1), std, __ldg(b1 + o)));
        h = fmaxf(h, 0.0f);
        z = fmaf(__ldg(W2 + o), h, z);
    }
    return 1.0f / (1.0f + __expf(-z));
}

__global__ void __launch_bounds__(NTHREADS, 8)
selfnorm_kernel(const float4* __restrict__ x,
                const float* __restrict__ W1m, const float* __restrict__ b1m,
                const float* __restrict__ W2m, const float* __restrict__ b2m,
                const float* __restrict__ W1s, const float* __restrict__ b1s,
                const float* __restrict__ W2s, const float* __restrict__ b2s,
                float4* __restrict__ out) {
    __shared__ float4 buf[F4];
    __shared__ float ps[8], psq[8];

    const int t    = threadIdx.x;
    const int lane = t & 31;
    const int wid  = t >> 5;

    const float4* __restrict__ xr   = x   + (size_t)blockIdx.x * F4;
    float4*       __restrict__ orow = out + (size_t)blockIdx.x * F4;

    // ---- Load once (streaming), buffer in smem, accumulate stats ----
    float s = 0.0f, sq = 0.0f;

    float4 a0 = __ldcs(xr + t);
    float4 a1 = __ldcs(xr + t + 256);
    float4 a2 = __ldcs(xr + t + 512);
    float4 a3;
    const bool rem = (t < 16);
    if (rem) a3 = __ldcs(xr + 768 + t);

    buf[t]       = a0;
    buf[t + 256] = a1;
    buf[t + 512] = a2;
    if (rem) buf[768 + t] = a3;

    s += a0.x + a0.y + a0.z + a0.w;
    sq = fmaf(a0.x, a0.x, sq); sq = fmaf(a0.y, a0.y, sq);
    sq = fmaf(a0.z, a0.z, sq); sq = fmaf(a0.w, a0.w, sq);
    s += a1.x + a1.y + a1.z + a1.w;
    sq = fmaf(a1.x, a1.x, sq); sq = fmaf(a1.y, a1.y, sq);
    sq = fmaf(a1.z, a1.z, sq); sq = fmaf(a1.w, a1.w, sq);
    s += a2.x + a2.y + a2.z + a2.w;
    sq = fmaf(a2.x, a2.x, sq); sq = fmaf(a2.y, a2.y, sq);
    sq = fmaf(a2.z, a2.z, sq); sq = fmaf(a2.w, a2.w, sq);
    if (rem) {
        s += a3.x + a3.y + a3.z + a3.w;
        sq = fmaf(a3.x, a3.x, sq); sq = fmaf(a3.y, a3.y, sq);
        sq = fmaf(a3.z, a3.z, sq); sq = fmaf(a3.w, a3.w, sq);
    }

    // ---- Warp reduce, then one barrier ----
    #pragma unroll
    for (int o = 16; o > 0; o >>= 1) {
        s  += __shfl_xor_sync(0xffffffffu, s,  o);
        sq += __shfl_xor_sync(0xffffffffu, sq, o);
    }
    if (lane == 0) { ps[wid] = s; psq[wid] = sq; }
    __syncthreads();

    // ---- Every thread: final sum + MLPs (redundant, no serialization) ----
    float ts = 0.0f, tsq = 0.0f;
    #pragma unroll
    for (int i = 0; i < 8; i++) { ts += ps[i]; tsq += psq[i]; }

    const float n = (float)HW;
    float mean = ts / n;
    float var  = (tsq - n * mean * mean) / (n - 1.0f);
    var = fmaxf(var, 0.0f);
    float std = sqrtf(var + EPS);

    float mean_w = tiny_mlp(mean, std, W1m, b1m, W2m, b2m);
    float std_w  = tiny_mlp(mean, std, W1s, b1s, W2s, b2s);

    const float alpha = std_w;
    const float beta  = mean * (mean_w - std_w);

    // ---- Transform from smem (own elements, no barrier) + streaming store ----
    #pragma unroll
    for (int i = 0; i < 3; i++) {
        float4 a = buf[t + 256 * i];
        float4 r;
        r.x = fmaf(a.x, alpha, beta);
        r.y = fmaf(a.y, alpha, beta);
        r.z = fmaf(a.z, alpha, beta);
        r.w = fmaf(a.w, alpha, beta);
        __stcs(orow + t + 256 * i, r);
    }
    if (rem) {
        float4 a = buf[768 + t];
        float4 r;
        r.x = fmaf(a.x, alpha, beta);
        r.y = fmaf(a.y, alpha, beta);
        r.z = fmaf(a.z, alpha, beta);
        r.w = fmaf(a.w, alpha, beta);
        __stcs(orow + 768 + t, r);
    }
}

extern "C" void kernel_launch(void* const* d_in, const int* in_sizes, int n_in,
                              void* d_out, int out_size) {
    const float4* x  = (const float4*)d_in[0];
    const float* W1m = (const float*)d_in[1];
    const float* b1m = (const float*)d_in[2];
    const float* W2m = (const float*)d_in[3];
    const float* b2m = (const float*)d_in[4];
    const float* W1s = (const float*)d_in[5];
    const float* b1s = (const float*)d_in[6];
    const float* W2s = (const float*)d_in[7];
    const float* b2s = (const float*)d_in[8];
    float4* out = (float4*)d_out;

    const int rows = 32 * 256;  // B * C = 8192 CTAs, one row each
    selfnorm_kernel<<<rows, NTHREADS>>>(x, W1m, b1m, W2m, b2m,
                                        W1s, b1s, W2s, b2s, out);
}